// round 10
// baseline (speedup 1.0000x reference)
#include <cuda_runtime.h>
#include <cuda_fp16.h>
#include <cstdint>

#define RR 5
#define BU 4
#define MAX_IN 1024
#define MAX_MU 64
#define MAX_OUT 256
#define MAX_N 50000
#define MAX_E 500000
#define NPART (2 * RR)
#define NBINS (NPART * MAX_N)
#define CAP 64                                  // per-bin slot capacity (Poisson(10))

// Static scratch. g_cnt relies on load-time zero-init; every kernel_launch
// leaves it zeroed again (gather re-zeros each bin after reading it).
__device__ __half g_Ph[RR * 3 * MAX_IN * MAX_OUT];              // 7.9 MB fp16 P
__device__ __half g_mh[2][(size_t)RR * MAX_N * MAX_OUT];        // 2 x 128 MB fp16 messages
__device__ int    g_cnt[NBINS];                                 // 2 MB  (invariant: 0 at entry)
__device__ int    g_pay[(size_t)NBINS * CAP];                   // 128 MB binned payload

// ---------------------------------------------------------------------------
// L1: fused k_P (blocks [0, pBlocks)) + combined hist/place (rest).
__global__ void k_fa(const float* __restrict__ att, const float* __restrict__ basis,
                     const float* __restrict__ fc_w,
                     const int* __restrict__ src, const int* __restrict__ dst,
                     int IN, int MU, int OUT, int E, int N, int pBlocks) {
    if ((int)blockIdx.x < pBlocks) {
        // ---- k_P: P[rk][i][o] = sum_m W[r][i][m] * fc_w[(rk*MU+m)*OUT+o]
        __shared__ float wrow[MAX_MU];
        int o  = threadIdx.x;
        int i  = blockIdx.x % IN;
        int rk = blockIdx.x / IN;
        int r  = rk / 3;
        if (o < MU) {
            float acc = 0.f;
#pragma unroll
            for (int b = 0; b < BU; b++)
                acc += att[r * BU + b] * basis[((size_t)b * IN + i) * MU + o];
            wrow[o] = acc;
        }
        __syncthreads();
        const float* fcb = fc_w + (size_t)(rk * MU) * OUT + o;
        float acc = 0.f;
#pragma unroll 8
        for (int m = 0; m < MU; m++)
            acc = fmaf(wrow[m], fcb[(size_t)m * OUT], acc);
        g_Ph[((size_t)rk * IN + i) * OUT + o] = __float2half_rn(acc);
    } else {
        // ---- place: 4 edges per thread (int4); single atomic = hist + place
        int t = (blockIdx.x - pBlocks) * blockDim.x + threadIdx.x;
        int eq = E >> 2;
        int tot = NPART * eq;
        if (t >= tot) return;
        int e4 = t % eq;
        int p  = t / eq;
        int r  = p % RR;
        const int* karr = (p < RR) ? dst : src;
        const int* parr = (p < RR) ? src : dst;
        int4 kk = *(const int4*)(karr + (size_t)r * E + 4 * e4);
        int4 pp = *(const int4*)(parr + (size_t)r * E + 4 * e4);
        int binb = p * N;
        {
            int bin = binb + kk.x;
            int pos = atomicAdd(&g_cnt[bin], 1);
            if (pos < CAP) g_pay[(size_t)bin * CAP + pos] = pp.x;
        }
        {
            int bin = binb + kk.y;
            int pos = atomicAdd(&g_cnt[bin], 1);
            if (pos < CAP) g_pay[(size_t)bin * CAP + pos] = pp.y;
        }
        {
            int bin = binb + kk.z;
            int pos = atomicAdd(&g_cnt[bin], 1);
            if (pos < CAP) g_pay[(size_t)bin * CAP + pos] = pp.z;
        }
        {
            int bin = binb + kk.w;
            int pos = atomicAdd(&g_cnt[bin], 1);
            if (pos < CAP) g_pay[(size_t)bin * CAP + pos] = pp.w;
        }
    }
}

// ---------------------------------------------------------------------------
// L2: messages for both node types, all ratings. One warp per (type, node).
// Round-6 structure: per-rating load-compute-store, fp32 converts, high occ.
__global__ void k_m(const int* __restrict__ drug_feat, const int* __restrict__ dis_feat,
                    const float* __restrict__ cj_drug, const float* __restrict__ cj_dis,
                    int N, int IN) {
    int gw = (blockIdx.x * blockDim.x + threadIdx.x) >> 5;
    int lane = threadIdx.x & 31;
    if (gw >= 2 * N) return;
    int type = gw >= N;
    int n = gw - type * N;
    const int* feat = type ? dis_feat : drug_feat;
    float c = (type ? cj_dis : cj_drug)[n];
    int f0 = feat[n * 3 + 0];
    int f1 = feat[n * 3 + 1];
    int f2 = feat[n * 3 + 2];
    int base = lane * 8;
    __half* mbase = g_mh[type] + (size_t)n * 256 + base;
#pragma unroll
    for (int r = 0; r < RR; r++) {
        uint4 ua = *(const uint4*)(g_Ph + ((size_t)(r * 3 + 0) * IN + f0) * 256 + base);
        uint4 ub = *(const uint4*)(g_Ph + ((size_t)(r * 3 + 1) * IN + f1) * 256 + base);
        uint4 ud = *(const uint4*)(g_Ph + ((size_t)(r * 3 + 2) * IN + f2) * 256 + base);
        uint4 pack;
        const unsigned int* pa = &ua.x;
        const unsigned int* pb = &ub.x;
        const unsigned int* pd = &ud.x;
        unsigned int* po = &pack.x;
#pragma unroll
        for (int q = 0; q < 4; q++) {
            float2 fa = __half22float2(*(const __half2*)&pa[q]);
            float2 fb = __half22float2(*(const __half2*)&pb[q]);
            float2 fd = __half22float2(*(const __half2*)&pd[q]);
            __half2 h = __floats2half2_rn(c * (fa.x + fb.x + fd.x),
                                          c * (fa.y + fb.y + fd.y));
            po[q] = *(const unsigned int*)&h;
        }
        *(uint4*)(mbase + (size_t)r * N * 256) = pack;
    }
}

// ---------------------------------------------------------------------------
// L3: fused gather, both directions. One warp per (dir, node).
// Bin counts read upfront, then re-zeroed (restores g_cnt==0 invariant).
__global__ void k_gather(const float* __restrict__ ci_dis, const float* __restrict__ ci_drug,
                         const float* __restrict__ bias,
                         float* __restrict__ out, int N, int gBlocks) {
    int dir = (int)blockIdx.x >= gBlocks;
    int bb_ = blockIdx.x - dir * gBlocks;
    int n = (bb_ * blockDim.x + threadIdx.x) >> 5;
    int lane = threadIdx.x & 31;
    if (n >= N) return;
    int base = lane * 8;
    float acc0 = 0.f, acc1 = 0.f, acc2 = 0.f, acc3 = 0.f;
    float acc4 = 0.f, acc5 = 0.f, acc6 = 0.f, acc7 = 0.f;

    int cnt[RR];
    int bin0 = dir * RR * N + n;
#pragma unroll
    for (int r = 0; r < RR; r++)
        cnt[r] = g_cnt[bin0 + r * N];
    // re-zero the bins this warp owns (one lane per bin)
    if (lane < RR) g_cnt[bin0 + lane * N] = 0;

#pragma unroll
    for (int r = 0; r < RR; r++) {
        int s1 = cnt[r] < CAP ? cnt[r] : CAP;
        const int* pb = g_pay + (size_t)(bin0 + r * N) * CAP;
        const __half* mb = g_mh[dir] + (size_t)r * N * 256;
        int j = 0;
        for (; j + 3 < s1; j += 4) {
            int sa = pb[j + 0];
            int sb = pb[j + 1];
            int sc = pb[j + 2];
            int sd = pb[j + 3];
            uint4 va = *(const uint4*)(mb + (size_t)sa * 256 + base);
            uint4 vb = *(const uint4*)(mb + (size_t)sb * 256 + base);
            uint4 vc = *(const uint4*)(mb + (size_t)sc * 256 + base);
            uint4 vd = *(const uint4*)(mb + (size_t)sd * 256 + base);
            float2 f;
            f = __half22float2(*(const __half2*)&va.x); acc0 += f.x; acc1 += f.y;
            f = __half22float2(*(const __half2*)&va.y); acc2 += f.x; acc3 += f.y;
            f = __half22float2(*(const __half2*)&va.z); acc4 += f.x; acc5 += f.y;
            f = __half22float2(*(const __half2*)&va.w); acc6 += f.x; acc7 += f.y;
            f = __half22float2(*(const __half2*)&vb.x); acc0 += f.x; acc1 += f.y;
            f = __half22float2(*(const __half2*)&vb.y); acc2 += f.x; acc3 += f.y;
            f = __half22float2(*(const __half2*)&vb.z); acc4 += f.x; acc5 += f.y;
            f = __half22float2(*(const __half2*)&vb.w); acc6 += f.x; acc7 += f.y;
            f = __half22float2(*(const __half2*)&vc.x); acc0 += f.x; acc1 += f.y;
            f = __half22float2(*(const __half2*)&vc.y); acc2 += f.x; acc3 += f.y;
            f = __half22float2(*(const __half2*)&vc.z); acc4 += f.x; acc5 += f.y;
            f = __half22float2(*(const __half2*)&vc.w); acc6 += f.x; acc7 += f.y;
            f = __half22float2(*(const __half2*)&vd.x); acc0 += f.x; acc1 += f.y;
            f = __half22float2(*(const __half2*)&vd.y); acc2 += f.x; acc3 += f.y;
            f = __half22float2(*(const __half2*)&vd.z); acc4 += f.x; acc5 += f.y;
            f = __half22float2(*(const __half2*)&vd.w); acc6 += f.x; acc7 += f.y;
        }
        for (; j < s1; j++) {
            int sa = pb[j];
            uint4 va = *(const uint4*)(mb + (size_t)sa * 256 + base);
            float2 f;
            f = __half22float2(*(const __half2*)&va.x); acc0 += f.x; acc1 += f.y;
            f = __half22float2(*(const __half2*)&va.y); acc2 += f.x; acc3 += f.y;
            f = __half22float2(*(const __half2*)&va.z); acc4 += f.x; acc5 += f.y;
            f = __half22float2(*(const __half2*)&va.w); acc6 += f.x; acc7 += f.y;
        }
    }

    const float* ci = dir ? ci_drug : ci_dis;
    float* outh = out + (dir ? 0 : (size_t)N * 256);
    float c = ci[n];
    const float4* bv = (const float4*)(bias + base);
    float4 bv0 = bv[0], bv1 = bv[1];
    float4 o0, o1;
    o0.x = acc0 * c + bv0.x;  o0.y = acc1 * c + bv0.y;
    o0.z = acc2 * c + bv0.z;  o0.w = acc3 * c + bv0.w;
    o1.x = acc4 * c + bv1.x;  o1.y = acc5 * c + bv1.y;
    o1.z = acc6 * c + bv1.z;  o1.w = acc7 * c + bv1.w;
    float4* op = (float4*)(outh + (size_t)n * 256 + base);
    op[0] = o0;
    op[1] = o1;
}

// ---------------------------------------------------------------------------
extern "C" void kernel_launch(void* const* d_in, const int* in_sizes, int n_in,
                              void* d_out, int out_size) {
    const int*   drug_feat = (const int*)d_in[0];
    const int*   dis_feat  = (const int*)d_in[1];
    const int*   src       = (const int*)d_in[2];
    const int*   dst       = (const int*)d_in[3];
    const float* cj_drug   = (const float*)d_in[4];
    const float* ci_drug   = (const float*)d_in[5];
    const float* cj_dis    = (const float*)d_in[6];
    const float* ci_dis    = (const float*)d_in[7];
    const float* att       = (const float*)d_in[8];
    const float* basis     = (const float*)d_in[9];
    const float* fc_w      = (const float*)d_in[10];
    const float* fc_b      = (const float*)d_in[11];
    float* out = (float*)d_out;

    const int N   = in_sizes[4];
    const int E   = in_sizes[2] / RR;
    const int OUT = in_sizes[11];
    const int MU  = in_sizes[10] / (OUT * 3 * RR);
    const int IN  = in_sizes[9] / (BU * MU);

    // L1: k_P + combined hist/place (g_cnt is zero by invariant)
    const int pBlocks = RR * 3 * IN;
    const int placeThreads = NPART * (E >> 2);
    const int placeBlocks = (placeThreads + 255) / 256;
    k_fa<<<pBlocks + placeBlocks, 256>>>(att, basis, fc_w, src, dst,
                                         IN, MU, OUT, E, N, pBlocks);

    // L2: messages
    const int mBlocks = (int)(((long long)2 * N * 32 + 255) / 256);
    k_m<<<mBlocks, 256>>>(drug_feat, dis_feat, cj_drug, cj_dis, N, IN);

    // L3: fused gather (both directions) + g_cnt re-zero
    const int gBlocks = (int)(((long long)N * 32 + 255) / 256);
    k_gather<<<2 * gBlocks, 256>>>(ci_dis, ci_drug, fc_b, out, N, gBlocks);
}

// round 11
// speedup vs baseline: 2.0826x; 2.0826x over previous
#include <cuda_runtime.h>
#include <cuda_fp16.h>
#include <cstdint>

#define RR 5
#define BU 4
#define MAX_IN 1024
#define MAX_MU 64
#define MAX_OUT 256
#define MAX_N 50000
#define MAX_E 500000
#define NPART (2 * RR)
#define NBINS (NPART * MAX_N)

// Static scratch (round-6 packed-CSR layout)
__device__ __half g_Ph[RR * 3 * MAX_IN * MAX_OUT];              // 7.9 MB fp16 P
__device__ __half g_mh[2][(size_t)RR * MAX_N * MAX_OUT];        // 2 x 128 MB fp16 messages
__device__ int    g_cnt[NBINS];
__device__ int    g_off[NBINS];      // scan1 incl -> scan3 excl -> place advances to END
__device__ int    g_pay[NPART * MAX_E];                         // packed payload
__device__ int    g_bsum[1024];

// ---------------------------------------------------------------------------
// Device helpers (round-6 bodies)
// ---------------------------------------------------------------------------
__device__ __forceinline__ void dev_m_node(int type, int n, int lane,
                                           const int* __restrict__ feat,
                                           const float* __restrict__ cj,
                                           int N, int IN) {
    float c = cj[n];
    int f0 = feat[n * 3 + 0];
    int f1 = feat[n * 3 + 1];
    int f2 = feat[n * 3 + 2];
    int base = lane * 8;
    __half* mbase = g_mh[type] + (size_t)n * 256 + base;
#pragma unroll
    for (int r = 0; r < RR; r++) {
        uint4 ua = *(const uint4*)(g_Ph + ((size_t)(r * 3 + 0) * IN + f0) * 256 + base);
        uint4 ub = *(const uint4*)(g_Ph + ((size_t)(r * 3 + 1) * IN + f1) * 256 + base);
        uint4 ud = *(const uint4*)(g_Ph + ((size_t)(r * 3 + 2) * IN + f2) * 256 + base);
        uint4 pack;
        const unsigned int* pa = &ua.x;
        const unsigned int* pb = &ub.x;
        const unsigned int* pd = &ud.x;
        unsigned int* po = &pack.x;
#pragma unroll
        for (int q = 0; q < 4; q++) {
            float2 fa = __half22float2(*(const __half2*)&pa[q]);
            float2 fb = __half22float2(*(const __half2*)&pb[q]);
            float2 fd = __half22float2(*(const __half2*)&pd[q]);
            __half2 h = __floats2half2_rn(c * (fa.x + fb.x + fd.x),
                                          c * (fa.y + fb.y + fd.y));
            po[q] = *(const unsigned int*)&h;
        }
        *(uint4*)(mbase + (size_t)r * N * 256) = pack;
    }
}

__device__ __forceinline__ void dev_gather_node(int dir, int n, int lane,
                                                const float* __restrict__ ci,
                                                const float* __restrict__ bias,
                                                float* __restrict__ outh, int N) {
    int base = lane * 8;
    float acc0 = 0.f, acc1 = 0.f, acc2 = 0.f, acc3 = 0.f;
    float acc4 = 0.f, acc5 = 0.f, acc6 = 0.f, acc7 = 0.f;

#pragma unroll
    for (int r = 0; r < RR; r++) {
        int bin = (dir * RR + r) * N + n;
        int s1 = g_off[bin];                 // end (post-place)
        int s0 = s1 - g_cnt[bin];
        const __half* mb = g_mh[dir] + (size_t)r * N * 256;
        int j = s0;
        for (; j + 3 < s1; j += 4) {
            int sa = g_pay[j + 0];
            int sb = g_pay[j + 1];
            int sc = g_pay[j + 2];
            int sd = g_pay[j + 3];
            uint4 va = *(const uint4*)(mb + (size_t)sa * 256 + base);
            uint4 vb = *(const uint4*)(mb + (size_t)sb * 256 + base);
            uint4 vc = *(const uint4*)(mb + (size_t)sc * 256 + base);
            uint4 vd = *(const uint4*)(mb + (size_t)sd * 256 + base);
            float2 f;
            f = __half22float2(*(const __half2*)&va.x); acc0 += f.x; acc1 += f.y;
            f = __half22float2(*(const __half2*)&va.y); acc2 += f.x; acc3 += f.y;
            f = __half22float2(*(const __half2*)&va.z); acc4 += f.x; acc5 += f.y;
            f = __half22float2(*(const __half2*)&va.w); acc6 += f.x; acc7 += f.y;
            f = __half22float2(*(const __half2*)&vb.x); acc0 += f.x; acc1 += f.y;
            f = __half22float2(*(const __half2*)&vb.y); acc2 += f.x; acc3 += f.y;
            f = __half22float2(*(const __half2*)&vb.z); acc4 += f.x; acc5 += f.y;
            f = __half22float2(*(const __half2*)&vb.w); acc6 += f.x; acc7 += f.y;
            f = __half22float2(*(const __half2*)&vc.x); acc0 += f.x; acc1 += f.y;
            f = __half22float2(*(const __half2*)&vc.y); acc2 += f.x; acc3 += f.y;
            f = __half22float2(*(const __half2*)&vc.z); acc4 += f.x; acc5 += f.y;
            f = __half22float2(*(const __half2*)&vc.w); acc6 += f.x; acc7 += f.y;
            f = __half22float2(*(const __half2*)&vd.x); acc0 += f.x; acc1 += f.y;
            f = __half22float2(*(const __half2*)&vd.y); acc2 += f.x; acc3 += f.y;
            f = __half22float2(*(const __half2*)&vd.z); acc4 += f.x; acc5 += f.y;
            f = __half22float2(*(const __half2*)&vd.w); acc6 += f.x; acc7 += f.y;
        }
        for (; j < s1; j++) {
            int sa = g_pay[j];
            uint4 va = *(const uint4*)(mb + (size_t)sa * 256 + base);
            float2 f;
            f = __half22float2(*(const __half2*)&va.x); acc0 += f.x; acc1 += f.y;
            f = __half22float2(*(const __half2*)&va.y); acc2 += f.x; acc3 += f.y;
            f = __half22float2(*(const __half2*)&va.z); acc4 += f.x; acc5 += f.y;
            f = __half22float2(*(const __half2*)&va.w); acc6 += f.x; acc7 += f.y;
        }
    }

    float c = ci[n];
    const float4* bv = (const float4*)(bias + base);
    float4 bv0 = bv[0], bv1 = bv[1];
    float4 o0, o1;
    o0.x = acc0 * c + bv0.x;  o0.y = acc1 * c + bv0.y;
    o0.z = acc2 * c + bv0.z;  o0.w = acc3 * c + bv0.w;
    o1.x = acc4 * c + bv1.x;  o1.y = acc5 * c + bv1.y;
    o1.z = acc6 * c + bv1.z;  o1.w = acc7 * c + bv1.w;
    float4* op = (float4*)(outh + (size_t)n * 256 + base);
    op[0] = o0;
    op[1] = o1;
}

// ---------------------------------------------------------------------------
// FA: fused k_P (blocks [0, pBlocks)) + 2-edge hist (round-6 exact).
__global__ void k_fa(const float* __restrict__ att, const float* __restrict__ basis,
                     const float* __restrict__ fc_w,
                     const int* __restrict__ src, const int* __restrict__ dst,
                     int IN, int MU, int OUT, int E, int N, int pBlocks) {
    if ((int)blockIdx.x < pBlocks) {
        __shared__ float wrow[MAX_MU];
        int o  = threadIdx.x;
        int i  = blockIdx.x % IN;
        int rk = blockIdx.x / IN;
        int r  = rk / 3;
        if (o < MU) {
            float acc = 0.f;
#pragma unroll
            for (int b = 0; b < BU; b++)
                acc += att[r * BU + b] * basis[((size_t)b * IN + i) * MU + o];
            wrow[o] = acc;
        }
        __syncthreads();
        const float* fcb = fc_w + (size_t)(rk * MU) * OUT + o;
        float acc = 0.f;
#pragma unroll 8
        for (int m = 0; m < MU; m++)
            acc = fmaf(wrow[m], fcb[(size_t)m * OUT], acc);
        g_Ph[((size_t)rk * IN + i) * OUT + o] = __float2half_rn(acc);
    } else {
        int t = (blockIdx.x - pBlocks) * blockDim.x + threadIdx.x;
        int eh = E >> 1;
        int half = NPART * eh;
        if (t >= half) return;
        int e2 = t % eh;
        int p  = t / eh;
        int r  = p % RR;
        const int* karr = (p < RR) ? dst : src;
        int2 kk = *(const int2*)(karr + (size_t)r * E + 2 * e2);
        atomicAdd(&g_cnt[p * N + kk.x], 1);
        atomicAdd(&g_cnt[p * N + kk.y], 1);
    }
}

// --------------------------- scan (round-6 exact) ---------------------------
__global__ void k_scan1(int n) {
    __shared__ int sh[512];
    int tid = threadIdx.x;
    int i = blockIdx.x * 512 + tid;
    int v = (i < n) ? g_cnt[i] : 0;
    sh[tid] = v;
    __syncthreads();
#pragma unroll
    for (int ofs = 1; ofs < 512; ofs <<= 1) {
        int t = (tid >= ofs) ? sh[tid - ofs] : 0;
        __syncthreads();
        sh[tid] += t;
        __syncthreads();
    }
    if (i < n) g_off[i] = sh[tid];
    if (tid == 511) g_bsum[blockIdx.x] = sh[511];
}

__global__ void k_scan3(int n) {
    __shared__ int ssum[8];
    int tid = threadIdx.x;
    int blk = blockIdx.x >> 1;
    int part = 0;
    for (int t = tid; t < blk; t += 256) part += g_bsum[t];
#pragma unroll
    for (int o = 16; o; o >>= 1) part += __shfl_down_sync(0xFFFFFFFFu, part, o);
    if ((tid & 31) == 0) ssum[tid >> 5] = part;
    __syncthreads();
    int S = 0;
#pragma unroll
    for (int w = 0; w < 8; w++) S += ssum[w];
    int i = blockIdx.x * 256 + tid;
    if (i < n) g_off[i] = g_off[i] - g_cnt[i] + S;
}

// ---------------------------------------------------------------------------
// FC: place (2-edge) interleaved with k_m(drug). P >= M assumed.
__global__ void k_fc(const int* __restrict__ src, const int* __restrict__ dst,
                     const int* __restrict__ drug_feat, const float* __restrict__ cj_drug,
                     int E, int N, int IN, int P, int M) {
    int bid = blockIdx.x;
    int placeIdx = -1, mIdx = -1;
    if (bid < 2 * M) {
        if (bid & 1) mIdx = bid >> 1;
        else placeIdx = bid >> 1;
    } else {
        placeIdx = bid - M;
    }

    if (placeIdx >= 0) {
        int t = placeIdx * blockDim.x + threadIdx.x;
        int eh = E >> 1;
        int half = NPART * eh;
        if (t >= half) return;
        int e2 = t % eh;
        int p  = t / eh;
        int r  = p % RR;
        const int* karr = (p < RR) ? dst : src;
        const int* parr = (p < RR) ? src : dst;
        int2 kk = *(const int2*)(karr + (size_t)r * E + 2 * e2);
        int2 pp = *(const int2*)(parr + (size_t)r * E + 2 * e2);
        int pos0 = atomicAdd(&g_off[p * N + kk.x], 1);
        g_pay[pos0] = pp.x;
        int pos1 = atomicAdd(&g_off[p * N + kk.y], 1);
        g_pay[pos1] = pp.y;
    } else {
        int gw = (mIdx * blockDim.x + threadIdx.x) >> 5;
        int lane = threadIdx.x & 31;
        if (gw >= N) return;
        dev_m_node(0, gw, lane, drug_feat, cj_drug, N, IN);
    }
}

// ---------------------------------------------------------------------------
// G1: k_m(dis) interleaved with gather dir0 (reads mh[0], done in FC).
__global__ void k_g1(const int* __restrict__ dis_feat, const float* __restrict__ cj_dis,
                     const float* __restrict__ ci_dis, const float* __restrict__ bias,
                     float* __restrict__ out, int N, int IN) {
    int bid = blockIdx.x;
    int lane = threadIdx.x & 31;
    if (bid & 1) {
        // gather dir0: drug -> dis, writes dis half
        int n = (((bid >> 1) * blockDim.x) + threadIdx.x) >> 5;
        if (n >= N) return;
        dev_gather_node(0, n, lane, ci_dis, bias, out + (size_t)N * 256, N);
    } else {
        int gw = (((bid >> 1) * blockDim.x) + threadIdx.x) >> 5;
        if (gw >= N) return;
        dev_m_node(1, gw, lane, dis_feat, cj_dis, N, IN);
    }
}

// G2: gather dir1 (dis -> drug), writes drug half.
__global__ void k_g2(const float* __restrict__ ci_drug, const float* __restrict__ bias,
                     float* __restrict__ out, int N) {
    int n = (blockIdx.x * blockDim.x + threadIdx.x) >> 5;
    int lane = threadIdx.x & 31;
    if (n >= N) return;
    dev_gather_node(1, n, lane, ci_drug, bias, out, N);
}

// ---------------------------------------------------------------------------
extern "C" void kernel_launch(void* const* d_in, const int* in_sizes, int n_in,
                              void* d_out, int out_size) {
    const int*   drug_feat = (const int*)d_in[0];
    const int*   dis_feat  = (const int*)d_in[1];
    const int*   src       = (const int*)d_in[2];
    const int*   dst       = (const int*)d_in[3];
    const float* cj_drug   = (const float*)d_in[4];
    const float* ci_drug   = (const float*)d_in[5];
    const float* cj_dis    = (const float*)d_in[6];
    const float* ci_dis    = (const float*)d_in[7];
    const float* att       = (const float*)d_in[8];
    const float* basis     = (const float*)d_in[9];
    const float* fc_w      = (const float*)d_in[10];
    const float* fc_b      = (const float*)d_in[11];
    float* out = (float*)d_out;

    const int N   = in_sizes[4];
    const int E   = in_sizes[2] / RR;
    const int OUT = in_sizes[11];
    const int MU  = in_sizes[10] / (OUT * 3 * RR);
    const int IN  = in_sizes[9] / (BU * MU);
    const int nbins = NPART * N;

    void* cntPtr = nullptr;
    cudaGetSymbolAddress(&cntPtr, g_cnt);
    cudaMemsetAsync(cntPtr, 0, (size_t)nbins * sizeof(int), 0);

    // FA: k_P + 2-edge hist
    const int pBlocks = RR * 3 * IN;
    const int histThreads = NPART * (E >> 1);
    const int histBlocks = (histThreads + 255) / 256;
    k_fa<<<pBlocks + histBlocks, 256>>>(att, basis, fc_w, src, dst,
                                        IN, MU, OUT, E, N, pBlocks);

    // scan
    k_scan1<<<(nbins + 511) / 512, 512>>>(nbins);
    k_scan3<<<(nbins + 255) / 256, 256>>>(nbins);

    // FC: place interleaved with k_m(drug)
    const int M = (int)(((long long)N * 32 + 255) / 256);   // node-warp blocks per type
    const int P = histBlocks;                               // place blocks (P >= M here)
    k_fc<<<P + M, 256>>>(src, dst, drug_feat, cj_drug, E, N, IN, P, M);

    // G1: k_m(dis) interleaved with gather dir0
    k_g1<<<2 * M, 256>>>(dis_feat, cj_dis, ci_dis, fc_b, out, N, IN);

    // G2: gather dir1
    k_g2<<<M, 256>>>(ci_drug, fc_b, out, N);
}

// round 12
// speedup vs baseline: 2.1628x; 1.0385x over previous
#include <cuda_runtime.h>
#include <cuda_fp16.h>
#include <cstdint>

#define RR 5
#define BU 4
#define MAX_IN 1024
#define MAX_MU 64
#define MAX_OUT 256
#define MAX_N 50000
#define MAX_E 500000
#define NPART (2 * RR)
#define NBINS (NPART * MAX_N)

// Static scratch (round-6 packed-CSR layout)
__device__ __half g_Ph[RR * 3 * MAX_IN * MAX_OUT];              // 7.9 MB fp16 P
__device__ __half g_mh[2][(size_t)RR * MAX_N * MAX_OUT];        // 2 x 128 MB fp16 messages
__device__ int    g_cnt[NBINS];
__device__ int    g_off[NBINS];      // scan1 incl -> scan3 excl -> place advances to END
__device__ int    g_pay[NPART * MAX_E];                         // packed payload
__device__ int    g_bsum[1024];

// ---------------------------------------------------------------------------
// Message body (round-6 exact)
__device__ __forceinline__ void dev_m_node(int type, int n, int lane,
                                           const int* __restrict__ feat,
                                           const float* __restrict__ cj,
                                           int N, int IN) {
    float c = cj[n];
    int f0 = feat[n * 3 + 0];
    int f1 = feat[n * 3 + 1];
    int f2 = feat[n * 3 + 2];
    int base = lane * 8;
    __half* mbase = g_mh[type] + (size_t)n * 256 + base;
#pragma unroll
    for (int r = 0; r < RR; r++) {
        uint4 ua = *(const uint4*)(g_Ph + ((size_t)(r * 3 + 0) * IN + f0) * 256 + base);
        uint4 ub = *(const uint4*)(g_Ph + ((size_t)(r * 3 + 1) * IN + f1) * 256 + base);
        uint4 ud = *(const uint4*)(g_Ph + ((size_t)(r * 3 + 2) * IN + f2) * 256 + base);
        uint4 pack;
        const unsigned int* pa = &ua.x;
        const unsigned int* pb = &ub.x;
        const unsigned int* pd = &ud.x;
        unsigned int* po = &pack.x;
#pragma unroll
        for (int q = 0; q < 4; q++) {
            float2 fa = __half22float2(*(const __half2*)&pa[q]);
            float2 fb = __half22float2(*(const __half2*)&pb[q]);
            float2 fd = __half22float2(*(const __half2*)&pd[q]);
            __half2 h = __floats2half2_rn(c * (fa.x + fb.x + fd.x),
                                          c * (fa.y + fb.y + fd.y));
            po[q] = *(const unsigned int*)&h;
        }
        *(uint4*)(mbase + (size_t)r * N * 256) = pack;
    }
}

// ---------------------------------------------------------------------------
// FA: fused k_P (blocks [0, pBlocks)) + int4 hist (rest).
__global__ void k_fa(const float* __restrict__ att, const float* __restrict__ basis,
                     const float* __restrict__ fc_w,
                     const int* __restrict__ src, const int* __restrict__ dst,
                     int IN, int MU, int OUT, int E, int N, int pBlocks) {
    if ((int)blockIdx.x < pBlocks) {
        __shared__ float wrow[MAX_MU];
        int o  = threadIdx.x;
        int i  = blockIdx.x % IN;
        int rk = blockIdx.x / IN;
        int r  = rk / 3;
        if (o < MU) {
            float acc = 0.f;
#pragma unroll
            for (int b = 0; b < BU; b++)
                acc += att[r * BU + b] * basis[((size_t)b * IN + i) * MU + o];
            wrow[o] = acc;
        }
        __syncthreads();
        const float* fcb = fc_w + (size_t)(rk * MU) * OUT + o;
        float acc = 0.f;
#pragma unroll 8
        for (int m = 0; m < MU; m++)
            acc = fmaf(wrow[m], fcb[(size_t)m * OUT], acc);
        g_Ph[((size_t)rk * IN + i) * OUT + o] = __float2half_rn(acc);
    } else {
        int t = (blockIdx.x - pBlocks) * blockDim.x + threadIdx.x;
        int eq = E >> 2;
        int tail = E & 3;
        int tot4 = NPART * eq;
        if (t < tot4) {
            int e4 = t % eq;
            int p  = t / eq;
            int r  = p % RR;
            const int* karr = (p < RR) ? dst : src;
            int4 kk = *(const int4*)(karr + (size_t)r * E + 4 * e4);
            int* cb = g_cnt + p * N;
            atomicAdd(&cb[kk.x], 1);
            atomicAdd(&cb[kk.y], 1);
            atomicAdd(&cb[kk.z], 1);
            atomicAdd(&cb[kk.w], 1);
        } else if (tail) {
            int t2 = t - tot4;
            if (t2 < NPART * tail) {
                int p = t2 / tail;
                int e = 4 * eq + t2 % tail;
                int r = p % RR;
                const int* karr = (p < RR) ? dst : src;
                atomicAdd(&g_cnt[p * N + karr[(size_t)r * E + e]], 1);
            }
        }
    }
}

// ---------------------------------------------------------------------------
// L2: scan1 (512-elem blocks) fused with m(drug). 512 threads.
__global__ void k_s1m(const int* __restrict__ drug_feat, const float* __restrict__ cj_drug,
                      int nbins, int N, int IN, int s1Blocks) {
    if ((int)blockIdx.x < s1Blocks) {
        __shared__ int sh[512];
        int tid = threadIdx.x;
        int i = blockIdx.x * 512 + tid;
        int v = (i < nbins) ? g_cnt[i] : 0;
        sh[tid] = v;
        __syncthreads();
#pragma unroll
        for (int ofs = 1; ofs < 512; ofs <<= 1) {
            int t = (tid >= ofs) ? sh[tid - ofs] : 0;
            __syncthreads();
            sh[tid] += t;
            __syncthreads();
        }
        if (i < nbins) g_off[i] = sh[tid];   // inclusive, temp
        if (tid == 511) g_bsum[blockIdx.x] = sh[511];
    } else {
        int gw = ((blockIdx.x - s1Blocks) * blockDim.x + threadIdx.x) >> 5;
        int lane = threadIdx.x & 31;
        if (gw >= N) return;
        dev_m_node(0, gw, lane, drug_feat, cj_drug, N, IN);
    }
}

// L3: scan3 (512-elem blocks; block-sum prefix by reduction) fused with m(dis).
__global__ void k_s3m(const int* __restrict__ dis_feat, const float* __restrict__ cj_dis,
                      int nbins, int N, int IN, int s3Blocks) {
    if ((int)blockIdx.x < s3Blocks) {
        __shared__ int ssum[16];
        int tid = threadIdx.x;
        int blk = blockIdx.x;                // 512-elem region index
        int part = 0;
        for (int t = tid; t < blk; t += 512) part += g_bsum[t];
#pragma unroll
        for (int o = 16; o; o >>= 1) part += __shfl_down_sync(0xFFFFFFFFu, part, o);
        if ((tid & 31) == 0) ssum[tid >> 5] = part;
        __syncthreads();
        int S = 0;
#pragma unroll
        for (int w = 0; w < 16; w++) S += ssum[w];
        int i = blk * 512 + tid;
        if (i < nbins) g_off[i] = g_off[i] - g_cnt[i] + S;   // exclusive offset
    } else {
        int gw = ((blockIdx.x - s3Blocks) * blockDim.x + threadIdx.x) >> 5;
        int lane = threadIdx.x & 31;
        if (gw >= N) return;
        dev_m_node(1, gw, lane, dis_feat, cj_dis, N, IN);
    }
}

// ---------------------------------------------------------------------------
// place: int4; atomically advance g_off; afterwards g_off[bin] == END of bin.
__global__ void k_place(const int* __restrict__ src, const int* __restrict__ dst,
                        int E, int N) {
    int t = blockIdx.x * blockDim.x + threadIdx.x;
    int eq = E >> 2;
    int tail = E & 3;
    int tot4 = NPART * eq;
    if (t < tot4) {
        int e4 = t % eq;
        int p  = t / eq;
        int r  = p % RR;
        const int* karr = (p < RR) ? dst : src;
        const int* parr = (p < RR) ? src : dst;
        int4 kk = *(const int4*)(karr + (size_t)r * E + 4 * e4);
        int4 pp = *(const int4*)(parr + (size_t)r * E + 4 * e4);
        int* ob = g_off + p * N;
        g_pay[atomicAdd(&ob[kk.x], 1)] = pp.x;
        g_pay[atomicAdd(&ob[kk.y], 1)] = pp.y;
        g_pay[atomicAdd(&ob[kk.z], 1)] = pp.z;
        g_pay[atomicAdd(&ob[kk.w], 1)] = pp.w;
    } else if (tail) {
        int t2 = t - tot4;
        if (t2 < NPART * tail) {
            int p = t2 / tail;
            int e = 4 * eq + t2 % tail;
            int r = p % RR;
            const int* karr = (p < RR) ? dst : src;
            const int* parr = (p < RR) ? src : dst;
            int key = karr[(size_t)r * E + e];
            int pay = parr[(size_t)r * E + e];
            g_pay[atomicAdd(&g_off[p * N + key], 1)] = pay;
        }
    }
}

// ---------------------------------------------------------------------------
// Fused gather (round-6 exact): both directions in one launch, warp per (dir,node).
__global__ void k_gather(const float* __restrict__ ci_dis, const float* __restrict__ ci_drug,
                         const float* __restrict__ bias,
                         float* __restrict__ out, int N, int gBlocks) {
    int dir = (int)blockIdx.x >= gBlocks;
    int bb_ = blockIdx.x - dir * gBlocks;
    int n = (bb_ * blockDim.x + threadIdx.x) >> 5;
    int lane = threadIdx.x & 31;
    if (n >= N) return;
    int base = lane * 8;
    float acc0 = 0.f, acc1 = 0.f, acc2 = 0.f, acc3 = 0.f;
    float acc4 = 0.f, acc5 = 0.f, acc6 = 0.f, acc7 = 0.f;

#pragma unroll
    for (int r = 0; r < RR; r++) {
        int bin = (dir * RR + r) * N + n;
        int s1 = g_off[bin];                 // end (post-place)
        int s0 = s1 - g_cnt[bin];
        const __half* mb = g_mh[dir] + (size_t)r * N * 256;
        int j = s0;
        for (; j + 3 < s1; j += 4) {
            int sa = g_pay[j + 0];
            int sb = g_pay[j + 1];
            int sc = g_pay[j + 2];
            int sd = g_pay[j + 3];
            uint4 va = *(const uint4*)(mb + (size_t)sa * 256 + base);
            uint4 vb = *(const uint4*)(mb + (size_t)sb * 256 + base);
            uint4 vc = *(const uint4*)(mb + (size_t)sc * 256 + base);
            uint4 vd = *(const uint4*)(mb + (size_t)sd * 256 + base);
            float2 f;
            f = __half22float2(*(const __half2*)&va.x); acc0 += f.x; acc1 += f.y;
            f = __half22float2(*(const __half2*)&va.y); acc2 += f.x; acc3 += f.y;
            f = __half22float2(*(const __half2*)&va.z); acc4 += f.x; acc5 += f.y;
            f = __half22float2(*(const __half2*)&va.w); acc6 += f.x; acc7 += f.y;
            f = __half22float2(*(const __half2*)&vb.x); acc0 += f.x; acc1 += f.y;
            f = __half22float2(*(const __half2*)&vb.y); acc2 += f.x; acc3 += f.y;
            f = __half22float2(*(const __half2*)&vb.z); acc4 += f.x; acc5 += f.y;
            f = __half22float2(*(const __half2*)&vb.w); acc6 += f.x; acc7 += f.y;
            f = __half22float2(*(const __half2*)&vc.x); acc0 += f.x; acc1 += f.y;
            f = __half22float2(*(const __half2*)&vc.y); acc2 += f.x; acc3 += f.y;
            f = __half22float2(*(const __half2*)&vc.z); acc4 += f.x; acc5 += f.y;
            f = __half22float2(*(const __half2*)&vc.w); acc6 += f.x; acc7 += f.y;
            f = __half22float2(*(const __half2*)&vd.x); acc0 += f.x; acc1 += f.y;
            f = __half22float2(*(const __half2*)&vd.y); acc2 += f.x; acc3 += f.y;
            f = __half22float2(*(const __half2*)&vd.z); acc4 += f.x; acc5 += f.y;
            f = __half22float2(*(const __half2*)&vd.w); acc6 += f.x; acc7 += f.y;
        }
        for (; j < s1; j++) {
            int sa = g_pay[j];
            uint4 va = *(const uint4*)(mb + (size_t)sa * 256 + base);
            float2 f;
            f = __half22float2(*(const __half2*)&va.x); acc0 += f.x; acc1 += f.y;
            f = __half22float2(*(const __half2*)&va.y); acc2 += f.x; acc3 += f.y;
            f = __half22float2(*(const __half2*)&va.z); acc4 += f.x; acc5 += f.y;
            f = __half22float2(*(const __half2*)&va.w); acc6 += f.x; acc7 += f.y;
        }
    }

    const float* ci = dir ? ci_drug : ci_dis;
    float* outh = out + (dir ? 0 : (size_t)N * 256);
    float c = ci[n];
    const float4* bv = (const float4*)(bias + base);
    float4 bv0 = bv[0], bv1 = bv[1];
    float4 o0, o1;
    o0.x = acc0 * c + bv0.x;  o0.y = acc1 * c + bv0.y;
    o0.z = acc2 * c + bv0.z;  o0.w = acc3 * c + bv0.w;
    o1.x = acc4 * c + bv1.x;  o1.y = acc5 * c + bv1.y;
    o1.z = acc6 * c + bv1.z;  o1.w = acc7 * c + bv1.w;
    float4* op = (float4*)(outh + (size_t)n * 256 + base);
    op[0] = o0;
    op[1] = o1;
}

// ---------------------------------------------------------------------------
extern "C" void kernel_launch(void* const* d_in, const int* in_sizes, int n_in,
                              void* d_out, int out_size) {
    const int*   drug_feat = (const int*)d_in[0];
    const int*   dis_feat  = (const int*)d_in[1];
    const int*   src       = (const int*)d_in[2];
    const int*   dst       = (const int*)d_in[3];
    const float* cj_drug   = (const float*)d_in[4];
    const float* ci_drug   = (const float*)d_in[5];
    const float* cj_dis    = (const float*)d_in[6];
    const float* ci_dis    = (const float*)d_in[7];
    const float* att       = (const float*)d_in[8];
    const float* basis     = (const float*)d_in[9];
    const float* fc_w      = (const float*)d_in[10];
    const float* fc_b      = (const float*)d_in[11];
    float* out = (float*)d_out;

    const int N   = in_sizes[4];
    const int E   = in_sizes[2] / RR;
    const int OUT = in_sizes[11];
    const int MU  = in_sizes[10] / (OUT * 3 * RR);
    const int IN  = in_sizes[9] / (BU * MU);
    const int nbins = NPART * N;

    void* cntPtr = nullptr;
    cudaGetSymbolAddress(&cntPtr, g_cnt);
    cudaMemsetAsync(cntPtr, 0, (size_t)nbins * sizeof(int), 0);

    // FA: k_P + int4 hist
    const int pBlocks = RR * 3 * IN;
    const int edgeThreads = NPART * (E >> 2) + NPART * (E & 3);
    const int edgeBlocks = (edgeThreads + 255) / 256;
    k_fa<<<pBlocks + edgeBlocks, 256>>>(att, basis, fc_w, src, dst,
                                        IN, MU, OUT, E, N, pBlocks);

    // L2: scan1 || m(drug);  L3: scan3 || m(dis)   (512 threads)
    const int sBlocks = (nbins + 511) / 512;
    const int mB512   = (int)(((long long)N * 32 + 511) / 512);
    k_s1m<<<sBlocks + mB512, 512>>>(drug_feat, cj_drug, nbins, N, IN, sBlocks);
    k_s3m<<<sBlocks + mB512, 512>>>(dis_feat, cj_dis, nbins, N, IN, sBlocks);

    // place (int4)
    k_place<<<edgeBlocks, 256>>>(src, dst, E, N);

    // Fused gather (both directions)
    const int gBlocks = (int)(((long long)N * 32 + 255) / 256);
    k_gather<<<2 * gBlocks, 256>>>(ci_dis, ci_drug, fc_b, out, N, gBlocks);
}